// round 12
// baseline (speedup 1.0000x reference)
#include <cuda_runtime.h>
#include <cuda_bf16.h>
#include <math.h>

#define N_NODES 100000
#define F_IN    1433
#define F_H     32
#define F_OUT   7
#define E_MAX   3400000

#define SCAN_TILE 1024
#define NB_SCAN ((N_NODES + SCAN_TILE - 1) / SCAN_TILE)   // 98

// ---------------- scratch (static device globals; no allocation) ----------------
__device__ float g_dinv[N_NODES];
__device__ float g_h   [N_NODES * F_H];     // x @ W1 (UNscaled)
__device__ float g_h2  [N_NODES * 8];       // (h1 @ W2) * dinv[row], padded 7->8
__device__ int   g_count [N_NODES];
__device__ int   g_row   [N_NODES + 1];
__device__ int   g_cursor[N_NODES];
__device__ int   g_ssrc  [E_MAX];
__device__ int   g_bsum  [NB_SCAN];
__device__ int   g_boff  [NB_SCAN];

__device__ __forceinline__ void mma_tf32(float* d, const unsigned* a, const unsigned* b) {
    asm volatile(
        "mma.sync.aligned.m16n8k8.row.col.f32.tf32.tf32.f32 "
        "{%0,%1,%2,%3}, {%4,%5,%6,%7}, {%8,%9}, {%0,%1,%2,%3};"
        : "+f"(d[0]), "+f"(d[1]), "+f"(d[2]), "+f"(d[3])
        : "r"(a[0]), "r"(a[1]), "r"(a[2]), "r"(a[3]), "r"(b[0]), "r"(b[1]));
}

__device__ __forceinline__ void cp_async16(void* smem_dst, const void* gsrc, int src_bytes) {
    unsigned saddr = (unsigned)__cvta_generic_to_shared(smem_dst);
    asm volatile("cp.async.cg.shared.global [%0], [%1], 16, %2;"
                 :: "r"(saddr), "l"(gsrc), "r"(src_bytes) : "memory");
}
__device__ __forceinline__ void cp_commit() { asm volatile("cp.async.commit_group;" ::: "memory"); }
__device__ __forceinline__ void cp_wait1()  { asm volatile("cp.async.wait_group 1;" ::: "memory"); }
__device__ __forceinline__ void cp_wait0()  { asm volatile("cp.async.wait_group 0;" ::: "memory"); }

// ---------------- CSR build ----------------
__global__ void zero_kernel() {
    int i = blockIdx.x * blockDim.x + threadIdx.x;
    if (i < N_NODES) g_count[i] = 0;
}

__global__ __launch_bounds__(256) void hist_kernel(const int* __restrict__ dst, int E) {
    int base = blockIdx.x * 1024 + threadIdx.x;
    #pragma unroll
    for (int k = 0; k < 4; ++k) {
        int e = base + k * 256;
        if (e < E) atomicAdd(&g_count[dst[e]], 1);
    }
}

// pass A: per-block local exclusive scan of g_count (1024 elems/block),
// writes local scan into g_row, block total into g_bsum, dinv inline.
__global__ __launch_bounds__(256) void scanA_kernel() {
    __shared__ int s_warp[8];
    int t = threadIdx.x;
    int lane = t & 31, wid = t >> 5;
    int base = blockIdx.x * SCAN_TILE + t * 4;

    int v[4];
    #pragma unroll
    for (int k = 0; k < 4; ++k) {
        int i = base + k;
        v[k] = (i < N_NODES) ? g_count[i] : 0;
    }
    int tsum = v[0] + v[1] + v[2] + v[3];

    int incl = tsum;
    #pragma unroll
    for (int off = 1; off < 32; off <<= 1) {
        int y = __shfl_up_sync(0xffffffffu, incl, off);
        if (lane >= off) incl += y;
    }
    if (lane == 31) s_warp[wid] = incl;
    __syncthreads();
    if (wid == 0 && lane < 8) {
        int w = s_warp[lane];
        #pragma unroll
        for (int off = 1; off < 8; off <<= 1) {
            int y = __shfl_up_sync(0xffu, w, off);
            if (lane >= off) w += y;
        }
        s_warp[lane] = w;
    }
    __syncthreads();
    int warpoff = (wid > 0) ? s_warp[wid - 1] : 0;
    int excl = warpoff + incl - tsum;

    int run = excl;
    #pragma unroll
    for (int k = 0; k < 4; ++k) {
        int i = base + k;
        if (i < N_NODES) {
            g_row[i]  = run;
            g_dinv[i] = rsqrtf((float)(v[k] + 1));
        }
        run += v[k];
    }
    if (t == 255) g_bsum[blockIdx.x] = s_warp[7];
}

__global__ __launch_bounds__(128) void scanB_kernel() {
    int t = threadIdx.x;
    int lane = t & 31, wid = t >> 5;
    __shared__ int s_warp[4];
    int v = (t < NB_SCAN) ? g_bsum[t] : 0;
    int incl = v;
    #pragma unroll
    for (int off = 1; off < 32; off <<= 1) {
        int y = __shfl_up_sync(0xffffffffu, incl, off);
        if (lane >= off) incl += y;
    }
    if (lane == 31) s_warp[wid] = incl;
    __syncthreads();
    if (wid == 0 && lane < 4) {
        int w = s_warp[lane];
        #pragma unroll
        for (int off = 1; off < 4; off <<= 1) {
            int y = __shfl_up_sync(0xfu, w, off);
            if (lane >= off) w += y;
        }
        s_warp[lane] = w;
    }
    __syncthreads();
    int warpoff = (wid > 0) ? s_warp[wid - 1] : 0;
    if (t < NB_SCAN) g_boff[t] = warpoff + incl - v;
    if (t == 0) g_row[N_NODES] = s_warp[3];
}

__global__ __launch_bounds__(256) void scanC_kernel() {
    int i = blockIdx.x * blockDim.x + threadIdx.x;
    if (i >= N_NODES) return;
    int r = g_row[i] + g_boff[i >> 10];
    g_row[i] = r;
    g_cursor[i] = r;
}

__global__ __launch_bounds__(256) void reorder_kernel(
    const int* __restrict__ src, const int* __restrict__ dst, int E)
{
    int base = blockIdx.x * 1024 + threadIdx.x;
    #pragma unroll
    for (int k = 0; k < 4; ++k) {
        int e = base + k * 256;
        if (e < E) {
            int d = dst[e];
            int s = src[e];
            int pos = atomicAdd(&g_cursor[d], 1);
            g_ssrc[pos] = s;
        }
    }
}

// ---------------- GEMM1 (tf32 tensor cores): h = x @ W1 (unscaled) ----------------
// R7 config: 128 threads / 4 warps, BM=128, 32 rows per warp, 2-stage cp.async.
// No dependency on the CSR build -> runs concurrently on a second stream.
#define BM 128
#define BK 32
#define XPITCH 36
#define WPITCH 40
#define NCHUNK ((F_IN + BK - 1) / BK)   // 45

__global__ __launch_bounds__(128) void gemm1_kernel(
    const float* __restrict__ x, const float* __restrict__ W1)
{
    __shared__ __align__(16) float Xs[2][BM][XPITCH];
    __shared__ __align__(16) float Ws[2][BK][WPITCH];

    const int tid  = threadIdx.x;
    const int lane = tid & 31;
    const int warp = tid >> 5;
    const int gid  = lane >> 2;
    const int tig  = lane & 3;
    const int row0 = blockIdx.x * BM;
    const int sh   = gid & 3;

    float acc[2][4][4];
    #pragma unroll
    for (int m = 0; m < 2; ++m)
        #pragma unroll
        for (int n = 0; n < 4; ++n)
            #pragma unroll
            for (int r = 0; r < 4; ++r) acc[m][n][r] = 0.f;

    auto issue_stage = [&](int chunk, int buf) {
        int k0 = chunk * BK;
        #pragma unroll
        for (int i = 0; i < 8; ++i) {
            int r  = i * 16 + (tid >> 3);
            int j0 = (tid & 7) * 4;
            int grow = row0 + r;
            const float* srcp = x;
            int valid = 0;
            if (grow < N_NODES) {
                int shift = grow & 3;
                int col = k0 - shift + j0;
                int vb = (F_IN - col) * 4;
                valid = vb < 0 ? 0 : (vb > 16 ? 16 : vb);
                srcp = x + ((size_t)grow * F_IN + col);
            }
            cp_async16(&Xs[buf][r][j0], srcp, valid);
        }
        {
            int r = tid;
            int grow = row0 + r;
            const float* srcp = x;
            int valid = 0;
            int shift = grow & 3;
            if (grow < N_NODES && shift > 0) {
                int col = k0 - shift + 32;
                int vb = (F_IN - col) * 4;
                valid = vb < 0 ? 0 : (vb > 16 ? 16 : vb);
                srcp = x + ((size_t)grow * F_IN + col);
            }
            cp_async16(&Xs[buf][r][32], srcp, valid);
        }
        #pragma unroll
        for (int i = 0; i < 2; ++i) {
            int lin = i * 128 + tid;
            int kw = lin >> 3;
            int j = lin & 7;
            int gk = k0 + kw;
            int valid = (gk < F_IN) ? 16 : 0;
            const float* srcp = W1 + (size_t)(valid ? gk : 0) * F_H + j * 4;
            cp_async16(&Ws[buf][kw][j * 4], srcp, valid);
        }
    };

    issue_stage(0, 0);
    cp_commit();

    for (int c = 0; c < NCHUNK; ++c) {
        int buf = c & 1;
        bool more = (c + 1 < NCHUNK);
        if (more) { issue_stage(c + 1, buf ^ 1); cp_commit(); }
        if (more) cp_wait1(); else cp_wait0();
        __syncthreads();

        const int wr = warp * 32;
        #pragma unroll
        for (int ks = 0; ks < 4; ++ks) {
            int kb = ks * 8;
            unsigned afr[2][4];
            #pragma unroll
            for (int m = 0; m < 2; ++m) {
                int rb = wr + m * 16;
                afr[m][0] = __float_as_uint(Xs[buf][rb + gid    ][kb + tig + sh    ]);
                afr[m][1] = __float_as_uint(Xs[buf][rb + gid + 8][kb + tig + sh    ]);
                afr[m][2] = __float_as_uint(Xs[buf][rb + gid    ][kb + tig + sh + 4]);
                afr[m][3] = __float_as_uint(Xs[buf][rb + gid + 8][kb + tig + sh + 4]);
            }
            #pragma unroll
            for (int n = 0; n < 4; ++n) {
                unsigned bfr[2];
                bfr[0] = __float_as_uint(Ws[buf][kb + tig    ][n * 8 + gid]);
                bfr[1] = __float_as_uint(Ws[buf][kb + tig + 4][n * 8 + gid]);
                mma_tf32(acc[0][n], afr[0], bfr);
                mma_tf32(acc[1][n], afr[1], bfr);
            }
        }
        __syncthreads();
    }

    #pragma unroll
    for (int m = 0; m < 2; ++m) {
        int r0r = row0 + warp * 32 + m * 16 + gid;
        int r1r = r0r + 8;
        #pragma unroll
        for (int n = 0; n < 4; ++n) {
            int col = n * 8 + tig * 2;
            if (r0r < N_NODES)
                *(float2*)&g_h[(size_t)r0r * F_H + col] =
                    make_float2(acc[m][n][0], acc[m][n][1]);
            if (r1r < N_NODES)
                *(float2*)&g_h[(size_t)r1r * F_H + col] =
                    make_float2(acc[m][n][2], acc[m][n][3]);
        }
    }
}

// ------- gather + node1 fused: 8 threads/node, 4-way unrolled, per-edge dinv -------
// agg = h[i]*di + sum_j h[s_j]*dinv[s_j]; h1 = relu(agg*di + b1); h2 = (h1@W2)*di
__global__ __launch_bounds__(256) void gather_node1_kernel(
    const float* __restrict__ b1, const float* __restrict__ W2)
{
    __shared__ float sW2[F_H * F_OUT];
    __shared__ float sb1[F_H];
    int tid = threadIdx.x;
    if (tid < F_H * F_OUT) sW2[tid] = W2[tid];
    if (tid < F_H)         sb1[tid] = b1[tid];
    __syncthreads();

    int i = blockIdx.x * 32 + (tid >> 3);
    int q = tid & 7;
    if (i >= N_NODES) return;

    int beg = g_row[i];
    int end = g_row[i + 1];
    float di = g_dinv[i];

    float4 acc = ((const float4*)(g_h + (size_t)i * F_H))[q];   // self term
    acc.x *= di; acc.y *= di; acc.z *= di; acc.w *= di;

    int j = beg;
    for (; j + 4 <= end; j += 4) {
        int s0 = __ldg(&g_ssrc[j    ]);
        int s1 = __ldg(&g_ssrc[j + 1]);
        int s2 = __ldg(&g_ssrc[j + 2]);
        int s3 = __ldg(&g_ssrc[j + 3]);
        float d0 = __ldg(&g_dinv[s0]);
        float d1 = __ldg(&g_dinv[s1]);
        float d2 = __ldg(&g_dinv[s2]);
        float d3 = __ldg(&g_dinv[s3]);
        float4 v0 = __ldg(((const float4*)(g_h + (size_t)s0 * F_H)) + q);
        float4 v1 = __ldg(((const float4*)(g_h + (size_t)s1 * F_H)) + q);
        float4 v2 = __ldg(((const float4*)(g_h + (size_t)s2 * F_H)) + q);
        float4 v3 = __ldg(((const float4*)(g_h + (size_t)s3 * F_H)) + q);
        acc.x += v0.x * d0 + v1.x * d1 + v2.x * d2 + v3.x * d3;
        acc.y += v0.y * d0 + v1.y * d1 + v2.y * d2 + v3.y * d3;
        acc.z += v0.z * d0 + v1.z * d1 + v2.z * d2 + v3.z * d3;
        acc.w += v0.w * d0 + v1.w * d1 + v2.w * d2 + v3.w * d3;
    }
    for (; j < end; ++j) {
        int s = __ldg(&g_ssrc[j]);
        float ds = __ldg(&g_dinv[s]);
        float4 v = __ldg(((const float4*)(g_h + (size_t)s * F_H)) + q);
        acc.x += v.x * ds; acc.y += v.y * ds;
        acc.z += v.z * ds; acc.w += v.w * ds;
    }

    float hv[4];
    hv[0] = fmaxf(acc.x * di + sb1[q * 4 + 0], 0.f);
    hv[1] = fmaxf(acc.y * di + sb1[q * 4 + 1], 0.f);
    hv[2] = fmaxf(acc.z * di + sb1[q * 4 + 2], 0.f);
    hv[3] = fmaxf(acc.w * di + sb1[q * 4 + 3], 0.f);

    float o[F_OUT];
    #pragma unroll
    for (int c = 0; c < F_OUT; ++c) o[c] = 0.f;
    #pragma unroll
    for (int t = 0; t < 4; ++t) {
        int f = q * 4 + t;
        #pragma unroll
        for (int c = 0; c < F_OUT; ++c)
            o[c] += hv[t] * sW2[f * F_OUT + c];
    }
    #pragma unroll
    for (int d = 4; d >= 1; d >>= 1)
        #pragma unroll
        for (int c = 0; c < F_OUT; ++c)
            o[c] += __shfl_down_sync(0xffffffffu, o[c], d, 8);

    if (q == 0) {
        float* outp = g_h2 + (size_t)i * 8;
        *(float4*)outp       = make_float4(o[0] * di, o[1] * di, o[2] * di, o[3] * di);
        *(float4*)(outp + 4) = make_float4(o[4] * di, o[5] * di, o[6] * di, 0.f);
    }
}

// ------- gather + final fused: 1 thread/node, 4-way unrolled -------
__global__ __launch_bounds__(256) void gather_final_kernel(
    const float* __restrict__ b2, float* __restrict__ out)
{
    int i = blockIdx.x * blockDim.x + threadIdx.x;
    if (i >= N_NODES) return;
    int beg = g_row[i];
    int end = g_row[i + 1];

    const float4* selfp = (const float4*)(g_h2 + (size_t)i * 8);
    float4 a0 = selfp[0];
    float4 a1 = selfp[1];
    int j = beg;
    for (; j + 4 <= end; j += 4) {
        int s0 = __ldg(&g_ssrc[j]);
        int s1 = __ldg(&g_ssrc[j + 1]);
        int s2 = __ldg(&g_ssrc[j + 2]);
        int s3 = __ldg(&g_ssrc[j + 3]);
        const float4* p0 = (const float4*)(g_h2 + (size_t)s0 * 8);
        const float4* p1 = (const float4*)(g_h2 + (size_t)s1 * 8);
        const float4* p2 = (const float4*)(g_h2 + (size_t)s2 * 8);
        const float4* p3 = (const float4*)(g_h2 + (size_t)s3 * 8);
        float4 u0 = __ldg(p0), u1 = __ldg(p0 + 1);
        float4 w0 = __ldg(p1), w1 = __ldg(p1 + 1);
        float4 y0 = __ldg(p2), y1 = __ldg(p2 + 1);
        float4 z0 = __ldg(p3), z1 = __ldg(p3 + 1);
        a0.x += (u0.x + w0.x) + (y0.x + z0.x);
        a0.y += (u0.y + w0.y) + (y0.y + z0.y);
        a0.z += (u0.z + w0.z) + (y0.z + z0.z);
        a0.w += (u0.w + w0.w) + (y0.w + z0.w);
        a1.x += (u1.x + w1.x) + (y1.x + z1.x);
        a1.y += (u1.y + w1.y) + (y1.y + z1.y);
        a1.z += (u1.z + w1.z) + (y1.z + z1.z);
    }
    for (; j < end; ++j) {
        int s = __ldg(&g_ssrc[j]);
        const float4* sp = (const float4*)(g_h2 + (size_t)s * 8);
        float4 v0 = __ldg(sp);
        float4 v1 = __ldg(sp + 1);
        a0.x += v0.x; a0.y += v0.y; a0.z += v0.z; a0.w += v0.w;
        a1.x += v1.x; a1.y += v1.y; a1.z += v1.z;
    }
    float di = g_dinv[i];
    float v[F_OUT];
    v[0] = a0.x * di + b2[0];
    v[1] = a0.y * di + b2[1];
    v[2] = a0.z * di + b2[2];
    v[3] = a0.w * di + b2[3];
    v[4] = a1.x * di + b2[4];
    v[5] = a1.y * di + b2[5];
    v[6] = a1.z * di + b2[6];
    float m = v[0];
    #pragma unroll
    for (int c = 1; c < F_OUT; ++c) m = fmaxf(m, v[c]);
    float s = 0.f;
    #pragma unroll
    for (int c = 0; c < F_OUT; ++c) s += expf(v[c] - m);
    float lse = m + logf(s);
    float* o = out + (size_t)i * F_OUT;
    #pragma unroll
    for (int c = 0; c < F_OUT; ++c) o[c] = v[c] - lse;
}

// ---------------- launch ----------------
extern "C" void kernel_launch(void* const* d_in, const int* in_sizes, int n_in,
                              void* d_out, int out_size)
{
    const float* x   = (const float*)d_in[0];
    const int*   ei  = (const int*)  d_in[1];
    const float* W1  = (const float*)d_in[2];
    const float* b1  = (const float*)d_in[3];
    const float* W2  = (const float*)d_in[4];
    const float* b2  = (const float*)d_in[5];
    float* out = (float*)d_out;

    const int E = in_sizes[1] / 2;
    const int* src = ei;
    const int* dst = ei + E;

    static cudaStream_t s2 = nullptr;
    static cudaEvent_t evFork = nullptr, evJoin = nullptr;
    if (!s2) {
        cudaStreamCreateWithFlags(&s2, cudaStreamNonBlocking);
        cudaEventCreateWithFlags(&evFork, cudaEventDisableTiming);
        cudaEventCreateWithFlags(&evJoin, cudaEventDisableTiming);
    }

    int nb_n  = (N_NODES + 255) / 256;
    int nb_e4 = (E + 1023) / 1024;
    int nb_g  = (N_NODES + BM - 1) / BM;

    // fork: gemm1 (independent of CSR) on s2
    cudaEventRecord(evFork, 0);
    cudaStreamWaitEvent(s2, evFork, 0);
    gemm1_kernel<<<nb_g, 128, 0, s2>>>(x, W1);
    cudaEventRecord(evJoin, s2);

    // CSR build on the main stream
    zero_kernel<<<nb_n, 256>>>();
    hist_kernel<<<nb_e4, 256>>>(dst, E);
    scanA_kernel<<<NB_SCAN, 256>>>();
    scanB_kernel<<<1, 128>>>();
    scanC_kernel<<<nb_n, 256>>>();
    reorder_kernel<<<nb_e4, 256>>>(src, dst, E);

    // join: gathers need both h and the CSR
    cudaStreamWaitEvent(0, evJoin, 0);

    gather_node1_kernel<<<(N_NODES + 31) / 32, 256>>>(b1, W2);
    gather_final_kernel<<<nb_n, 256>>>(b2, out);
}

// round 14
// speedup vs baseline: 1.3032x; 1.3032x over previous
#include <cuda_runtime.h>
#include <cuda_bf16.h>
#include <math.h>

#define N_NODES 100000
#define F_IN    1433
#define F_H     32
#define F_OUT   7
#define E_MAX   3400000

#define SCAN_TILE 1024
#define NB_SCAN ((N_NODES + SCAN_TILE - 1) / SCAN_TILE)   // 98

// ---------------- scratch (static device globals; no allocation) ----------------
__device__ float g_dinv[N_NODES];
__device__ float g_h   [N_NODES * F_H];     // (x @ W1) * dinv[row]
__device__ float g_h2  [N_NODES * 8];       // (h1 @ W2) * dinv[row], padded 7->8
__device__ int   g_count [N_NODES];
__device__ int   g_row   [N_NODES + 1];
__device__ int   g_cursor[N_NODES];
__device__ int   g_ssrc  [E_MAX];
__device__ int   g_bsum  [NB_SCAN];
__device__ int   g_boff  [NB_SCAN];

__device__ __forceinline__ void mma_tf32(float* d, const unsigned* a, const unsigned* b) {
    asm volatile(
        "mma.sync.aligned.m16n8k8.row.col.f32.tf32.tf32.f32 "
        "{%0,%1,%2,%3}, {%4,%5,%6,%7}, {%8,%9}, {%0,%1,%2,%3};"
        : "+f"(d[0]), "+f"(d[1]), "+f"(d[2]), "+f"(d[3])
        : "r"(a[0]), "r"(a[1]), "r"(a[2]), "r"(a[3]), "r"(b[0]), "r"(b[1]));
}

__device__ __forceinline__ void cp_async16(void* smem_dst, const void* gsrc, int src_bytes) {
    unsigned saddr = (unsigned)__cvta_generic_to_shared(smem_dst);
    asm volatile("cp.async.cg.shared.global [%0], [%1], 16, %2;"
                 :: "r"(saddr), "l"(gsrc), "r"(src_bytes) : "memory");
}
__device__ __forceinline__ void cp_commit() { asm volatile("cp.async.commit_group;" ::: "memory"); }
__device__ __forceinline__ void cp_wait1()  { asm volatile("cp.async.wait_group 1;" ::: "memory"); }
__device__ __forceinline__ void cp_wait0()  { asm volatile("cp.async.wait_group 0;" ::: "memory"); }

// ---------------- CSR build ----------------
__global__ void zero_kernel() {
    int i = blockIdx.x * blockDim.x + threadIdx.x;
    if (i < N_NODES) g_count[i] = 0;
}

__global__ __launch_bounds__(256) void hist_kernel(const int* __restrict__ dst, int E) {
    int base = blockIdx.x * 1024 + threadIdx.x;
    #pragma unroll
    for (int k = 0; k < 4; ++k) {
        int e = base + k * 256;
        if (e < E) atomicAdd(&g_count[dst[e]], 1);
    }
}

// pass A: per-block local exclusive scan of g_count (1024 elems/block),
// writes local scan into g_row, block total into g_bsum, dinv inline.
__global__ __launch_bounds__(256) void scanA_kernel() {
    __shared__ int s_warp[8];
    int t = threadIdx.x;
    int lane = t & 31, wid = t >> 5;
    int base = blockIdx.x * SCAN_TILE + t * 4;

    int v[4];
    #pragma unroll
    for (int k = 0; k < 4; ++k) {
        int i = base + k;
        v[k] = (i < N_NODES) ? g_count[i] : 0;
    }
    int tsum = v[0] + v[1] + v[2] + v[3];

    int incl = tsum;
    #pragma unroll
    for (int off = 1; off < 32; off <<= 1) {
        int y = __shfl_up_sync(0xffffffffu, incl, off);
        if (lane >= off) incl += y;
    }
    if (lane == 31) s_warp[wid] = incl;
    __syncthreads();
    if (wid == 0 && lane < 8) {
        int w = s_warp[lane];
        #pragma unroll
        for (int off = 1; off < 8; off <<= 1) {
            int y = __shfl_up_sync(0xffu, w, off);
            if (lane >= off) w += y;
        }
        s_warp[lane] = w;
    }
    __syncthreads();
    int warpoff = (wid > 0) ? s_warp[wid - 1] : 0;
    int excl = warpoff + incl - tsum;

    int run = excl;
    #pragma unroll
    for (int k = 0; k < 4; ++k) {
        int i = base + k;
        if (i < N_NODES) {
            g_row[i]  = run;
            g_dinv[i] = rsqrtf((float)(v[k] + 1));
        }
        run += v[k];
    }
    if (t == 255) g_bsum[blockIdx.x] = s_warp[7];
}

__global__ __launch_bounds__(128) void scanB_kernel() {
    int t = threadIdx.x;
    int lane = t & 31, wid = t >> 5;
    __shared__ int s_warp[4];
    int v = (t < NB_SCAN) ? g_bsum[t] : 0;
    int incl = v;
    #pragma unroll
    for (int off = 1; off < 32; off <<= 1) {
        int y = __shfl_up_sync(0xffffffffu, incl, off);
        if (lane >= off) incl += y;
    }
    if (lane == 31) s_warp[wid] = incl;
    __syncthreads();
    if (wid == 0 && lane < 4) {
        int w = s_warp[lane];
        #pragma unroll
        for (int off = 1; off < 4; off <<= 1) {
            int y = __shfl_up_sync(0xfu, w, off);
            if (lane >= off) w += y;
        }
        s_warp[lane] = w;
    }
    __syncthreads();
    int warpoff = (wid > 0) ? s_warp[wid - 1] : 0;
    if (t < NB_SCAN) g_boff[t] = warpoff + incl - v;
    if (t == 0) g_row[N_NODES] = s_warp[3];
}

__global__ __launch_bounds__(256) void scanC_kernel() {
    int i = blockIdx.x * blockDim.x + threadIdx.x;
    if (i >= N_NODES) return;
    int r = g_row[i] + g_boff[i >> 10];
    g_row[i] = r;
    g_cursor[i] = r;
}

__global__ __launch_bounds__(256) void reorder_kernel(
    const int* __restrict__ src, const int* __restrict__ dst, int E)
{
    int base = blockIdx.x * 1024 + threadIdx.x;
    #pragma unroll
    for (int k = 0; k < 4; ++k) {
        int e = base + k * 256;
        if (e < E) {
            int d = dst[e];
            int s = src[e];
            int pos = atomicAdd(&g_cursor[d], 1);
            g_ssrc[pos] = s;
        }
    }
}

// ---------------- GEMM1 (tf32 tensor cores): h = (x @ W1) * dinv ----------------
// R7 pipeline config (128 threads / 4 warps / 2-stage), but each CTA now
// processes TWO row tiles so the whole grid (391 CTAs) fits in ONE wave
// (resident capacity = 148 SMs x 4 CTAs = 592), removing the 1.32-wave tail.
#define BM 128
#define BK 32
#define XPITCH 36
#define WPITCH 40
#define NCHUNK ((F_IN + BK - 1) / BK)   // 45
#define NTILE ((N_NODES + BM - 1) / BM) // 782

__global__ __launch_bounds__(128) void gemm1_kernel(
    const float* __restrict__ x, const float* __restrict__ W1)
{
    __shared__ __align__(16) float Xs[2][BM][XPITCH];
    __shared__ __align__(16) float Ws[2][BK][WPITCH];

    const int tid  = threadIdx.x;
    const int lane = tid & 31;
    const int warp = tid >> 5;
    const int gid  = lane >> 2;
    const int tig  = lane & 3;
    const int sh   = gid & 3;

    for (int tile = blockIdx.x * 2; tile < min(blockIdx.x * 2 + 2, NTILE); ++tile) {
        const int row0 = tile * BM;

        float acc[2][4][4];
        #pragma unroll
        for (int m = 0; m < 2; ++m)
            #pragma unroll
            for (int n = 0; n < 4; ++n)
                #pragma unroll
                for (int r = 0; r < 4; ++r) acc[m][n][r] = 0.f;

        auto issue_stage = [&](int chunk, int buf) {
            int k0 = chunk * BK;
            #pragma unroll
            for (int i = 0; i < 8; ++i) {
                int r  = i * 16 + (tid >> 3);
                int j0 = (tid & 7) * 4;
                int grow = row0 + r;
                const float* srcp = x;
                int valid = 0;
                if (grow < N_NODES) {
                    int shift = grow & 3;
                    int col = k0 - shift + j0;
                    int vb = (F_IN - col) * 4;
                    valid = vb < 0 ? 0 : (vb > 16 ? 16 : vb);
                    srcp = x + ((size_t)grow * F_IN + col);
                }
                cp_async16(&Xs[buf][r][j0], srcp, valid);
            }
            {
                int r = tid;
                int grow = row0 + r;
                const float* srcp = x;
                int valid = 0;
                int shift = grow & 3;
                if (grow < N_NODES && shift > 0) {
                    int col = k0 - shift + 32;
                    int vb = (F_IN - col) * 4;
                    valid = vb < 0 ? 0 : (vb > 16 ? 16 : vb);
                    srcp = x + ((size_t)grow * F_IN + col);
                }
                cp_async16(&Xs[buf][r][32], srcp, valid);
            }
            #pragma unroll
            for (int i = 0; i < 2; ++i) {
                int lin = i * 128 + tid;
                int kw = lin >> 3;
                int j = lin & 7;
                int gk = k0 + kw;
                int valid = (gk < F_IN) ? 16 : 0;
                const float* srcp = W1 + (size_t)(valid ? gk : 0) * F_H + j * 4;
                cp_async16(&Ws[buf][kw][j * 4], srcp, valid);
            }
        };

        issue_stage(0, 0);
        cp_commit();

        for (int c = 0; c < NCHUNK; ++c) {
            int buf = c & 1;
            bool more = (c + 1 < NCHUNK);
            if (more) { issue_stage(c + 1, buf ^ 1); cp_commit(); }
            if (more) cp_wait1(); else cp_wait0();
            __syncthreads();

            const int wr = warp * 32;
            #pragma unroll
            for (int ks = 0; ks < 4; ++ks) {
                int kb = ks * 8;
                unsigned afr[2][4];
                #pragma unroll
                for (int m = 0; m < 2; ++m) {
                    int rb = wr + m * 16;
                    afr[m][0] = __float_as_uint(Xs[buf][rb + gid    ][kb + tig + sh    ]);
                    afr[m][1] = __float_as_uint(Xs[buf][rb + gid + 8][kb + tig + sh    ]);
                    afr[m][2] = __float_as_uint(Xs[buf][rb + gid    ][kb + tig + sh + 4]);
                    afr[m][3] = __float_as_uint(Xs[buf][rb + gid + 8][kb + tig + sh + 4]);
                }
                #pragma unroll
                for (int n = 0; n < 4; ++n) {
                    unsigned bfr[2];
                    bfr[0] = __float_as_uint(Ws[buf][kb + tig    ][n * 8 + gid]);
                    bfr[1] = __float_as_uint(Ws[buf][kb + tig + 4][n * 8 + gid]);
                    mma_tf32(acc[0][n], afr[0], bfr);
                    mma_tf32(acc[1][n], afr[1], bfr);
                }
            }
            __syncthreads();
        }

        #pragma unroll
        for (int m = 0; m < 2; ++m) {
            int r0r = row0 + warp * 32 + m * 16 + gid;
            int r1r = r0r + 8;
            float w0 = (r0r < N_NODES) ? g_dinv[r0r] : 0.f;
            float w1 = (r1r < N_NODES) ? g_dinv[r1r] : 0.f;
            #pragma unroll
            for (int n = 0; n < 4; ++n) {
                int col = n * 8 + tig * 2;
                if (r0r < N_NODES)
                    *(float2*)&g_h[(size_t)r0r * F_H + col] =
                        make_float2(acc[m][n][0] * w0, acc[m][n][1] * w0);
                if (r1r < N_NODES)
                    *(float2*)&g_h[(size_t)r1r * F_H + col] =
                        make_float2(acc[m][n][2] * w1, acc[m][n][3] * w1);
            }
        }
    }
}

// ------- gather + node1 fused: 8 threads/node, 4-way unrolled gather -------
__global__ __launch_bounds__(256) void gather_node1_kernel(
    const float* __restrict__ b1, const float* __restrict__ W2)
{
    __shared__ float sW2[F_H * F_OUT];
    __shared__ float sb1[F_H];
    int tid = threadIdx.x;
    if (tid < F_H * F_OUT) sW2[tid] = W2[tid];
    if (tid < F_H)         sb1[tid] = b1[tid];
    __syncthreads();

    int i = blockIdx.x * 32 + (tid >> 3);
    int q = tid & 7;
    if (i >= N_NODES) return;

    int beg = g_row[i];
    int end = g_row[i + 1];

    float4 acc = ((const float4*)(g_h + (size_t)i * F_H))[q];   // self term

    int j = beg;
    for (; j + 4 <= end; j += 4) {
        int s0 = __ldg(&g_ssrc[j    ]);
        int s1 = __ldg(&g_ssrc[j + 1]);
        int s2 = __ldg(&g_ssrc[j + 2]);
        int s3 = __ldg(&g_ssrc[j + 3]);
        float4 v0 = __ldg(((const float4*)(g_h + (size_t)s0 * F_H)) + q);
        float4 v1 = __ldg(((const float4*)(g_h + (size_t)s1 * F_H)) + q);
        float4 v2 = __ldg(((const float4*)(g_h + (size_t)s2 * F_H)) + q);
        float4 v3 = __ldg(((const float4*)(g_h + (size_t)s3 * F_H)) + q);
        acc.x += v0.x + v1.x + v2.x + v3.x;
        acc.y += v0.y + v1.y + v2.y + v3.y;
        acc.z += v0.z + v1.z + v2.z + v3.z;
        acc.w += v0.w + v1.w + v2.w + v3.w;
    }
    for (; j < end; ++j) {
        int s = __ldg(&g_ssrc[j]);
        float4 v = __ldg(((const float4*)(g_h + (size_t)s * F_H)) + q);
        acc.x += v.x; acc.y += v.y; acc.z += v.z; acc.w += v.w;
    }

    float di = g_dinv[i];
    float hv[4];
    hv[0] = fmaxf(acc.x * di + sb1[q * 4 + 0], 0.f);
    hv[1] = fmaxf(acc.y * di + sb1[q * 4 + 1], 0.f);
    hv[2] = fmaxf(acc.z * di + sb1[q * 4 + 2], 0.f);
    hv[3] = fmaxf(acc.w * di + sb1[q * 4 + 3], 0.f);

    float o[F_OUT];
    #pragma unroll
    for (int c = 0; c < F_OUT; ++c) o[c] = 0.f;
    #pragma unroll
    for (int t = 0; t < 4; ++t) {
        int f = q * 4 + t;
        #pragma unroll
        for (int c = 0; c < F_OUT; ++c)
            o[c] += hv[t] * sW2[f * F_OUT + c];
    }
    #pragma unroll
    for (int d = 4; d >= 1; d >>= 1)
        #pragma unroll
        for (int c = 0; c < F_OUT; ++c)
            o[c] += __shfl_down_sync(0xffffffffu, o[c], d, 8);

    if (q == 0) {
        float* outp = g_h2 + (size_t)i * 8;
        *(float4*)outp       = make_float4(o[0] * di, o[1] * di, o[2] * di, o[3] * di);
        *(float4*)(outp + 4) = make_float4(o[4] * di, o[5] * di, o[6] * di, 0.f);
    }
}

// ------- gather + final fused: 1 thread/node, 4-way unrolled -------
__global__ __launch_bounds__(256) void gather_final_kernel(
    const float* __restrict__ b2, float* __restrict__ out)
{
    int i = blockIdx.x * blockDim.x + threadIdx.x;
    if (i >= N_NODES) return;
    int beg = g_row[i];
    int end = g_row[i + 1];

    const float4* selfp = (const float4*)(g_h2 + (size_t)i * 8);
    float4 a0 = selfp[0];
    float4 a1 = selfp[1];
    int j = beg;
    for (; j + 4 <= end; j += 4) {
        int s0 = __ldg(&g_ssrc[j]);
        int s1 = __ldg(&g_ssrc[j + 1]);
        int s2 = __ldg(&g_ssrc[j + 2]);
        int s3 = __ldg(&g_ssrc[j + 3]);
        const float4* p0 = (const float4*)(g_h2 + (size_t)s0 * 8);
        const float4* p1 = (const float4*)(g_h2 + (size_t)s1 * 8);
        const float4* p2 = (const float4*)(g_h2 + (size_t)s2 * 8);
        const float4* p3 = (const float4*)(g_h2 + (size_t)s3 * 8);
        float4 u0 = __ldg(p0), u1 = __ldg(p0 + 1);
        float4 w0 = __ldg(p1), w1 = __ldg(p1 + 1);
        float4 y0 = __ldg(p2), y1 = __ldg(p2 + 1);
        float4 z0 = __ldg(p3), z1 = __ldg(p3 + 1);
        a0.x += (u0.x + w0.x) + (y0.x + z0.x);
        a0.y += (u0.y + w0.y) + (y0.y + z0.y);
        a0.z += (u0.z + w0.z) + (y0.z + z0.z);
        a0.w += (u0.w + w0.w) + (y0.w + z0.w);
        a1.x += (u1.x + w1.x) + (y1.x + z1.x);
        a1.y += (u1.y + w1.y) + (y1.y + z1.y);
        a1.z += (u1.z + w1.z) + (y1.z + z1.z);
    }
    for (; j < end; ++j) {
        int s = __ldg(&g_ssrc[j]);
        const float4* sp = (const float4*)(g_h2 + (size_t)s * 8);
        float4 v0 = __ldg(sp);
        float4 v1 = __ldg(sp + 1);
        a0.x += v0.x; a0.y += v0.y; a0.z += v0.z; a0.w += v0.w;
        a1.x += v1.x; a1.y += v1.y; a1.z += v1.z;
    }
    float di = g_dinv[i];
    float v[F_OUT];
    v[0] = a0.x * di + b2[0];
    v[1] = a0.y * di + b2[1];
    v[2] = a0.z * di + b2[2];
    v[3] = a0.w * di + b2[3];
    v[4] = a1.x * di + b2[4];
    v[5] = a1.y * di + b2[5];
    v[6] = a1.z * di + b2[6];
    float m = v[0];
    #pragma unroll
    for (int c = 1; c < F_OUT; ++c) m = fmaxf(m, v[c]);
    float s = 0.f;
    #pragma unroll
    for (int c = 0; c < F_OUT; ++c) s += expf(v[c] - m);
    float lse = m + logf(s);
    float* o = out + (size_t)i * F_OUT;
    #pragma unroll
    for (int c = 0; c < F_OUT; ++c) o[c] = v[c] - lse;
}

// ---------------- launch ----------------
extern "C" void kernel_launch(void* const* d_in, const int* in_sizes, int n_in,
                              void* d_out, int out_size)
{
    const float* x   = (const float*)d_in[0];
    const int*   ei  = (const int*)  d_in[1];
    const float* W1  = (const float*)d_in[2];
    const float* b1  = (const float*)d_in[3];
    const float* W2  = (const float*)d_in[4];
    const float* b2  = (const float*)d_in[5];
    float* out = (float*)d_out;

    const int E = in_sizes[1] / 2;
    const int* src = ei;
    const int* dst = ei + E;

    int nb_n  = (N_NODES + 255) / 256;
    int nb_e4 = (E + 1023) / 1024;

    zero_kernel<<<nb_n, 256>>>();
    hist_kernel<<<nb_e4, 256>>>(dst, E);
    scanA_kernel<<<NB_SCAN, 256>>>();
    scanB_kernel<<<1, 128>>>();
    scanC_kernel<<<nb_n, 256>>>();
    reorder_kernel<<<nb_e4, 256>>>(src, dst, E);

    gemm1_kernel<<<(NTILE + 1) / 2, 128>>>(x, W1);

    gather_node1_kernel<<<(N_NODES + 31) / 32, 256>>>(b1, W2);

    gather_final_kernel<<<nb_n, 256>>>(b2, out);
}

// round 16
// speedup vs baseline: 1.3989x; 1.0734x over previous
#include <cuda_runtime.h>
#include <cuda_fp16.h>
#include <math.h>

#define N_NODES 100000
#define F_IN    1433
#define F_H     32
#define F_OUT   7
#define E_MAX   3400000

#define SCAN_TILE 1024
#define NB_SCAN ((N_NODES + SCAN_TILE - 1) / SCAN_TILE)   // 98

// ---------------- scratch (static device globals; no allocation) ----------------
__device__ float  g_dinv[N_NODES];
__device__ __half g_hh [N_NODES * F_H];    // (x @ W1) * dinv[row], fp16
__device__ __half g_h2h[N_NODES * 8];      // (h1 @ W2) * dinv[row], fp16, padded 7->8
__device__ int    g_count [N_NODES];
__device__ int    g_row   [N_NODES + 1];
__device__ int    g_cursor[N_NODES];
__device__ int    g_ssrc  [E_MAX];
__device__ int    g_bsum  [NB_SCAN];
__device__ int    g_boff  [NB_SCAN];

__device__ __forceinline__ void mma_tf32(float* d, const unsigned* a, const unsigned* b) {
    asm volatile(
        "mma.sync.aligned.m16n8k8.row.col.f32.tf32.tf32.f32 "
        "{%0,%1,%2,%3}, {%4,%5,%6,%7}, {%8,%9}, {%0,%1,%2,%3};"
        : "+f"(d[0]), "+f"(d[1]), "+f"(d[2]), "+f"(d[3])
        : "r"(a[0]), "r"(a[1]), "r"(a[2]), "r"(a[3]), "r"(b[0]), "r"(b[1]));
}

__device__ __forceinline__ void cp_async16(void* smem_dst, const void* gsrc, int src_bytes) {
    unsigned saddr = (unsigned)__cvta_generic_to_shared(smem_dst);
    asm volatile("cp.async.cg.shared.global [%0], [%1], 16, %2;"
                 :: "r"(saddr), "l"(gsrc), "r"(src_bytes) : "memory");
}
__device__ __forceinline__ void cp_commit() { asm volatile("cp.async.commit_group;" ::: "memory"); }
__device__ __forceinline__ void cp_wait1()  { asm volatile("cp.async.wait_group 1;" ::: "memory"); }
__device__ __forceinline__ void cp_wait0()  { asm volatile("cp.async.wait_group 0;" ::: "memory"); }

// ---------------- CSR build ----------------
__global__ void zero_kernel() {
    int i = blockIdx.x * blockDim.x + threadIdx.x;
    if (i < N_NODES) g_count[i] = 0;
}

__global__ __launch_bounds__(256) void hist_kernel(const int* __restrict__ dst, int E) {
    int base = blockIdx.x * 1024 + threadIdx.x;
    #pragma unroll
    for (int k = 0; k < 4; ++k) {
        int e = base + k * 256;
        if (e < E) atomicAdd(&g_count[dst[e]], 1);
    }
}

__global__ __launch_bounds__(256) void scanA_kernel() {
    __shared__ int s_warp[8];
    int t = threadIdx.x;
    int lane = t & 31, wid = t >> 5;
    int base = blockIdx.x * SCAN_TILE + t * 4;

    int v[4];
    #pragma unroll
    for (int k = 0; k < 4; ++k) {
        int i = base + k;
        v[k] = (i < N_NODES) ? g_count[i] : 0;
    }
    int tsum = v[0] + v[1] + v[2] + v[3];

    int incl = tsum;
    #pragma unroll
    for (int off = 1; off < 32; off <<= 1) {
        int y = __shfl_up_sync(0xffffffffu, incl, off);
        if (lane >= off) incl += y;
    }
    if (lane == 31) s_warp[wid] = incl;
    __syncthreads();
    if (wid == 0 && lane < 8) {
        int w = s_warp[lane];
        #pragma unroll
        for (int off = 1; off < 8; off <<= 1) {
            int y = __shfl_up_sync(0xffu, w, off);
            if (lane >= off) w += y;
        }
        s_warp[lane] = w;
    }
    __syncthreads();
    int warpoff = (wid > 0) ? s_warp[wid - 1] : 0;
    int excl = warpoff + incl - tsum;

    int run = excl;
    #pragma unroll
    for (int k = 0; k < 4; ++k) {
        int i = base + k;
        if (i < N_NODES) {
            g_row[i]  = run;
            g_dinv[i] = rsqrtf((float)(v[k] + 1));
        }
        run += v[k];
    }
    if (t == 255) g_bsum[blockIdx.x] = s_warp[7];
}

__global__ __launch_bounds__(128) void scanB_kernel() {
    int t = threadIdx.x;
    int lane = t & 31, wid = t >> 5;
    __shared__ int s_warp[4];
    int v = (t < NB_SCAN) ? g_bsum[t] : 0;
    int incl = v;
    #pragma unroll
    for (int off = 1; off < 32; off <<= 1) {
        int y = __shfl_up_sync(0xffffffffu, incl, off);
        if (lane >= off) incl += y;
    }
    if (lane == 31) s_warp[wid] = incl;
    __syncthreads();
    if (wid == 0 && lane < 4) {
        int w = s_warp[lane];
        #pragma unroll
        for (int off = 1; off < 4; off <<= 1) {
            int y = __shfl_up_sync(0xfu, w, off);
            if (lane >= off) w += y;
        }
        s_warp[lane] = w;
    }
    __syncthreads();
    int warpoff = (wid > 0) ? s_warp[wid - 1] : 0;
    if (t < NB_SCAN) g_boff[t] = warpoff + incl - v;
    if (t == 0) g_row[N_NODES] = s_warp[3];
}

__global__ __launch_bounds__(256) void scanC_kernel() {
    int i = blockIdx.x * blockDim.x + threadIdx.x;
    if (i >= N_NODES) return;
    int r = g_row[i] + g_boff[i >> 10];
    g_row[i] = r;
    g_cursor[i] = r;
}

__global__ __launch_bounds__(256) void reorder_kernel(
    const int* __restrict__ src, const int* __restrict__ dst, int E)
{
    int base = blockIdx.x * 1024 + threadIdx.x;
    #pragma unroll
    for (int k = 0; k < 4; ++k) {
        int e = base + k * 256;
        if (e < E) {
            int d = dst[e];
            int s = src[e];
            int pos = atomicAdd(&g_cursor[d], 1);
            g_ssrc[pos] = s;
        }
    }
}

// ---------------- GEMM1 (tf32 tensor cores): h = (x @ W1) * dinv -> fp16 ----------------
#define BM 128
#define BK 32
#define XPITCH 36
#define WPITCH 40
#define NCHUNK ((F_IN + BK - 1) / BK)   // 45

__global__ __launch_bounds__(128) void gemm1_kernel(
    const float* __restrict__ x, const float* __restrict__ W1)
{
    __shared__ __align__(16) float Xs[2][BM][XPITCH];
    __shared__ __align__(16) float Ws[2][BK][WPITCH];

    const int tid  = threadIdx.x;
    const int lane = tid & 31;
    const int warp = tid >> 5;
    const int gid  = lane >> 2;
    const int tig  = lane & 3;
    const int row0 = blockIdx.x * BM;
    const int sh   = gid & 3;

    float acc[2][4][4];
    #pragma unroll
    for (int m = 0; m < 2; ++m)
        #pragma unroll
        for (int n = 0; n < 4; ++n)
            #pragma unroll
            for (int r = 0; r < 4; ++r) acc[m][n][r] = 0.f;

    auto issue_stage = [&](int chunk, int buf) {
        int k0 = chunk * BK;
        #pragma unroll
        for (int i = 0; i < 8; ++i) {
            int r  = i * 16 + (tid >> 3);
            int j0 = (tid & 7) * 4;
            int grow = row0 + r;
            const float* srcp = x;
            int valid = 0;
            if (grow < N_NODES) {
                int shift = grow & 3;
                int col = k0 - shift + j0;
                int vb = (F_IN - col) * 4;
                valid = vb < 0 ? 0 : (vb > 16 ? 16 : vb);
                srcp = x + ((size_t)grow * F_IN + col);
            }
            cp_async16(&Xs[buf][r][j0], srcp, valid);
        }
        {
            int r = tid;
            int grow = row0 + r;
            const float* srcp = x;
            int valid = 0;
            int shift = grow & 3;
            if (grow < N_NODES && shift > 0) {
                int col = k0 - shift + 32;
                int vb = (F_IN - col) * 4;
                valid = vb < 0 ? 0 : (vb > 16 ? 16 : vb);
                srcp = x + ((size_t)grow * F_IN + col);
            }
            cp_async16(&Xs[buf][r][32], srcp, valid);
        }
        #pragma unroll
        for (int i = 0; i < 2; ++i) {
            int lin = i * 128 + tid;
            int kw = lin >> 3;
            int j = lin & 7;
            int gk = k0 + kw;
            int valid = (gk < F_IN) ? 16 : 0;
            const float* srcp = W1 + (size_t)(valid ? gk : 0) * F_H + j * 4;
            cp_async16(&Ws[buf][kw][j * 4], srcp, valid);
        }
    };

    issue_stage(0, 0);
    cp_commit();

    for (int c = 0; c < NCHUNK; ++c) {
        int buf = c & 1;
        bool more = (c + 1 < NCHUNK);
        if (more) { issue_stage(c + 1, buf ^ 1); cp_commit(); }
        if (more) cp_wait1(); else cp_wait0();
        __syncthreads();

        const int wr = warp * 32;
        #pragma unroll
        for (int ks = 0; ks < 4; ++ks) {
            int kb = ks * 8;
            unsigned afr[2][4];
            #pragma unroll
            for (int m = 0; m < 2; ++m) {
                int rb = wr + m * 16;
                afr[m][0] = __float_as_uint(Xs[buf][rb + gid    ][kb + tig + sh    ]);
                afr[m][1] = __float_as_uint(Xs[buf][rb + gid + 8][kb + tig + sh    ]);
                afr[m][2] = __float_as_uint(Xs[buf][rb + gid    ][kb + tig + sh + 4]);
                afr[m][3] = __float_as_uint(Xs[buf][rb + gid + 8][kb + tig + sh + 4]);
            }
            #pragma unroll
            for (int n = 0; n < 4; ++n) {
                unsigned bfr[2];
                bfr[0] = __float_as_uint(Ws[buf][kb + tig    ][n * 8 + gid]);
                bfr[1] = __float_as_uint(Ws[buf][kb + tig + 4][n * 8 + gid]);
                mma_tf32(acc[0][n], afr[0], bfr);
                mma_tf32(acc[1][n], afr[1], bfr);
            }
        }
        __syncthreads();
    }

    // epilogue: scale by dinv[row], convert to fp16, store __half2
    #pragma unroll
    for (int m = 0; m < 2; ++m) {
        int r0r = row0 + warp * 32 + m * 16 + gid;
        int r1r = r0r + 8;
        float w0 = (r0r < N_NODES) ? g_dinv[r0r] : 0.f;
        float w1 = (r1r < N_NODES) ? g_dinv[r1r] : 0.f;
        #pragma unroll
        for (int n = 0; n < 4; ++n) {
            int col = n * 8 + tig * 2;
            if (r0r < N_NODES)
                *(__half2*)&g_hh[(size_t)r0r * F_H + col] =
                    __floats2half2_rn(acc[m][n][0] * w0, acc[m][n][1] * w0);
            if (r1r < N_NODES)
                *(__half2*)&g_hh[(size_t)r1r * F_H + col] =
                    __floats2half2_rn(acc[m][n][2] * w1, acc[m][n][3] * w1);
        }
    }
}

// ------- gather + node1 fused: 8 threads/node, 4-way unrolled, fp16 h -------
__device__ __forceinline__ void acc_half4(float4& a, uint2 p) {
    float2 lo = __half22float2(*(__half2*)&p.x);
    float2 hi = __half22float2(*(__half2*)&p.y);
    a.x += lo.x; a.y += lo.y; a.z += hi.x; a.w += hi.y;
}

__global__ __launch_bounds__(256) void gather_node1_kernel(
    const float* __restrict__ b1, const float* __restrict__ W2)
{
    __shared__ float sW2[F_H * F_OUT];
    __shared__ float sb1[F_H];
    int tid = threadIdx.x;
    if (tid < F_H * F_OUT) sW2[tid] = W2[tid];
    if (tid < F_H)         sb1[tid] = b1[tid];
    __syncthreads();

    int i = blockIdx.x * 32 + (tid >> 3);
    int q = tid & 7;
    if (i >= N_NODES) return;

    int beg = g_row[i];
    int end = g_row[i + 1];

    float4 acc = make_float4(0.f, 0.f, 0.f, 0.f);
    // self term
    acc_half4(acc, __ldg(((const uint2*)(g_hh + (size_t)i * F_H)) + q));

    int j = beg;
    for (; j + 4 <= end; j += 4) {
        int s0 = __ldg(&g_ssrc[j    ]);
        int s1 = __ldg(&g_ssrc[j + 1]);
        int s2 = __ldg(&g_ssrc[j + 2]);
        int s3 = __ldg(&g_ssrc[j + 3]);
        uint2 p0 = __ldg(((const uint2*)(g_hh + (size_t)s0 * F_H)) + q);
        uint2 p1 = __ldg(((const uint2*)(g_hh + (size_t)s1 * F_H)) + q);
        uint2 p2 = __ldg(((const uint2*)(g_hh + (size_t)s2 * F_H)) + q);
        uint2 p3 = __ldg(((const uint2*)(g_hh + (size_t)s3 * F_H)) + q);
        acc_half4(acc, p0);
        acc_half4(acc, p1);
        acc_half4(acc, p2);
        acc_half4(acc, p3);
    }
    for (; j < end; ++j) {
        int s = __ldg(&g_ssrc[j]);
        acc_half4(acc, __ldg(((const uint2*)(g_hh + (size_t)s * F_H)) + q));
    }

    float di = g_dinv[i];
    float hv[4];
    hv[0] = fmaxf(acc.x * di + sb1[q * 4 + 0], 0.f);
    hv[1] = fmaxf(acc.y * di + sb1[q * 4 + 1], 0.f);
    hv[2] = fmaxf(acc.z * di + sb1[q * 4 + 2], 0.f);
    hv[3] = fmaxf(acc.w * di + sb1[q * 4 + 3], 0.f);

    float o[F_OUT];
    #pragma unroll
    for (int c = 0; c < F_OUT; ++c) o[c] = 0.f;
    #pragma unroll
    for (int t = 0; t < 4; ++t) {
        int f = q * 4 + t;
        #pragma unroll
        for (int c = 0; c < F_OUT; ++c)
            o[c] += hv[t] * sW2[f * F_OUT + c];
    }
    #pragma unroll
    for (int d = 4; d >= 1; d >>= 1)
        #pragma unroll
        for (int c = 0; c < F_OUT; ++c)
            o[c] += __shfl_down_sync(0xffffffffu, o[c], d, 8);

    if (q == 0) {
        // pack 8 fp16 (7 outputs + pad) as uint4, scaled by di
        __half2 p0 = __floats2half2_rn(o[0] * di, o[1] * di);
        __half2 p1 = __floats2half2_rn(o[2] * di, o[3] * di);
        __half2 p2 = __floats2half2_rn(o[4] * di, o[5] * di);
        __half2 p3 = __floats2half2_rn(o[6] * di, 0.f);
        uint4 pk;
        pk.x = *(unsigned*)&p0; pk.y = *(unsigned*)&p1;
        pk.z = *(unsigned*)&p2; pk.w = *(unsigned*)&p3;
        *(uint4*)(g_h2h + (size_t)i * 8) = pk;
    }
}

// ------- gather + final fused: 1 thread/node, 4-way unrolled, fp16 h2 -------
__device__ __forceinline__ void acc_half8(float* a, uint4 p) {
    float2 f0 = __half22float2(*(__half2*)&p.x);
    float2 f1 = __half22float2(*(__half2*)&p.y);
    float2 f2 = __half22float2(*(__half2*)&p.z);
    float2 f3 = __half22float2(*(__half2*)&p.w);
    a[0] += f0.x; a[1] += f0.y; a[2] += f1.x; a[3] += f1.y;
    a[4] += f2.x; a[5] += f2.y; a[6] += f3.x;
}

__global__ __launch_bounds__(256) void gather_final_kernel(
    const float* __restrict__ b2, float* __restrict__ out)
{
    int i = blockIdx.x * blockDim.x + threadIdx.x;
    if (i >= N_NODES) return;
    int beg = g_row[i];
    int end = g_row[i + 1];

    float a[F_OUT];
    #pragma unroll
    for (int c = 0; c < F_OUT; ++c) a[c] = 0.f;
    acc_half8(a, __ldg((const uint4*)(g_h2h + (size_t)i * 8)));   // self

    int j = beg;
    for (; j + 4 <= end; j += 4) {
        int s0 = __ldg(&g_ssrc[j]);
        int s1 = __ldg(&g_ssrc[j + 1]);
        int s2 = __ldg(&g_ssrc[j + 2]);
        int s3 = __ldg(&g_ssrc[j + 3]);
        uint4 p0 = __ldg((const uint4*)(g_h2h + (size_t)s0 * 8));
        uint4 p1 = __ldg((const uint4*)(g_h2h + (size_t)s1 * 8));
        uint4 p2 = __ldg((const uint4*)(g_h2h + (size_t)s2 * 8));
        uint4 p3 = __ldg((const uint4*)(g_h2h + (size_t)s3 * 8));
        acc_half8(a, p0);
        acc_half8(a, p1);
        acc_half8(a, p2);
        acc_half8(a, p3);
    }
    for (; j < end; ++j) {
        int s = __ldg(&g_ssrc[j]);
        acc_half8(a, __ldg((const uint4*)(g_h2h + (size_t)s * 8)));
    }

    float di = g_dinv[i];
    float v[F_OUT];
    #pragma unroll
    for (int c = 0; c < F_OUT; ++c) v[c] = a[c] * di + b2[c];
    float m = v[0];
    #pragma unroll
    for (int c = 1; c < F_OUT; ++c) m = fmaxf(m, v[c]);
    float s = 0.f;
    #pragma unroll
    for (int c = 0; c < F_OUT; ++c) s += expf(v[c] - m);
    float lse = m + logf(s);
    float* o = out + (size_t)i * F_OUT;
    #pragma unroll
    for (int c = 0; c < F_OUT; ++c) o[c] = v[c] - lse;
}

// ---------------- launch ----------------
extern "C" void kernel_launch(void* const* d_in, const int* in_sizes, int n_in,
                              void* d_out, int out_size)
{
    const float* x   = (const float*)d_in[0];
    const int*   ei  = (const int*)  d_in[1];
    const float* W1  = (const float*)d_in[2];
    const float* b1  = (const float*)d_in[3];
    const float* W2  = (const float*)d_in[4];
    const float* b2  = (const float*)d_in[5];
    float* out = (float*)d_out;

    const int E = in_sizes[1] / 2;
    const int* src = ei;
    const int* dst = ei + E;

    int nb_n  = (N_NODES + 255) / 256;
    int nb_e4 = (E + 1023) / 1024;

    zero_kernel<<<nb_n, 256>>>();
    hist_kernel<<<nb_e4, 256>>>(dst, E);
    scanA_kernel<<<NB_SCAN, 256>>>();
    scanB_kernel<<<1, 128>>>();
    scanC_kernel<<<nb_n, 256>>>();
    reorder_kernel<<<nb_e4, 256>>>(src, dst, E);

    int nb_g = (N_NODES + BM - 1) / BM;
    gemm1_kernel<<<nb_g, 128>>>(x, W1);

    gather_node1_kernel<<<(N_NODES + 31) / 32, 256>>>(b1, W2);

    gather_final_kernel<<<nb_n, 256>>>(b2, out);
}

// round 17
// speedup vs baseline: 1.3991x; 1.0001x over previous
#include <cuda_runtime.h>
#include <cuda_fp16.h>
#include <math.h>

#define N_NODES 100000
#define F_IN    1433
#define F_H     32
#define F_OUT   7
#define E_MAX   3400000

#define SCAN_TILE 1024
#define NB_SCAN ((N_NODES + SCAN_TILE - 1) / SCAN_TILE)   // 98

// ---------------- scratch (static device globals; no allocation) ----------------
__device__ float  g_dinv[N_NODES];
__device__ __half g_hh [N_NODES * F_H];    // (x @ W1) * dinv[row], fp16
__device__ __half g_h2h[N_NODES * 8];      // (h1 @ W2) * dinv[row], fp16, padded 7->8
__device__ int    g_count [N_NODES];
__device__ int    g_row   [N_NODES + 1];
__device__ int    g_cursor[N_NODES];
__device__ int    g_ssrc  [E_MAX];
__device__ int    g_bsum  [NB_SCAN];
__device__ int    g_boff  [NB_SCAN];

__device__ __forceinline__ void mma_tf32(float* d, const unsigned* a, const unsigned* b) {
    asm volatile(
        "mma.sync.aligned.m16n8k8.row.col.f32.tf32.tf32.f32 "
        "{%0,%1,%2,%3}, {%4,%5,%6,%7}, {%8,%9}, {%0,%1,%2,%3};"
        : "+f"(d[0]), "+f"(d[1]), "+f"(d[2]), "+f"(d[3])
        : "r"(a[0]), "r"(a[1]), "r"(a[2]), "r"(a[3]), "r"(b[0]), "r"(b[1]));
}

__device__ __forceinline__ void cp_async16(void* smem_dst, const void* gsrc, int src_bytes) {
    unsigned saddr = (unsigned)__cvta_generic_to_shared(smem_dst);
    asm volatile("cp.async.cg.shared.global [%0], [%1], 16, %2;"
                 :: "r"(saddr), "l"(gsrc), "r"(src_bytes) : "memory");
}
__device__ __forceinline__ void cp_commit() { asm volatile("cp.async.commit_group;" ::: "memory"); }
__device__ __forceinline__ void cp_wait1()  { asm volatile("cp.async.wait_group 1;" ::: "memory"); }
__device__ __forceinline__ void cp_wait0()  { asm volatile("cp.async.wait_group 0;" ::: "memory"); }

// ---------------- CSR build ----------------
__global__ void zero_kernel() {
    int i = blockIdx.x * blockDim.x + threadIdx.x;
    if (i < N_NODES) g_count[i] = 0;
}

// 4 edges per thread via one int4 load
__global__ __launch_bounds__(256) void hist_kernel(const int* __restrict__ dst, int E) {
    int t = blockIdx.x * 256 + threadIdx.x;
    int base = t * 4;
    if (base + 3 < E) {
        int4 d = __ldg((const int4*)(dst + base));
        atomicAdd(&g_count[d.x], 1);
        atomicAdd(&g_count[d.y], 1);
        atomicAdd(&g_count[d.z], 1);
        atomicAdd(&g_count[d.w], 1);
    } else {
        for (int e = base; e < E; ++e) atomicAdd(&g_count[dst[e]], 1);
    }
}

// pass A: per-block local exclusive scan of g_count (1024 elems/block),
// writes local scan into g_row, block total into g_bsum, dinv inline.
__global__ __launch_bounds__(256) void scanA_kernel() {
    __shared__ int s_warp[8];
    int t = threadIdx.x;
    int lane = t & 31, wid = t >> 5;
    int base = blockIdx.x * SCAN_TILE + t * 4;

    int v[4];
    #pragma unroll
    for (int k = 0; k < 4; ++k) {
        int i = base + k;
        v[k] = (i < N_NODES) ? g_count[i] : 0;
    }
    int tsum = v[0] + v[1] + v[2] + v[3];

    int incl = tsum;
    #pragma unroll
    for (int off = 1; off < 32; off <<= 1) {
        int y = __shfl_up_sync(0xffffffffu, incl, off);
        if (lane >= off) incl += y;
    }
    if (lane == 31) s_warp[wid] = incl;
    __syncthreads();
    if (wid == 0 && lane < 8) {
        int w = s_warp[lane];
        #pragma unroll
        for (int off = 1; off < 8; off <<= 1) {
            int y = __shfl_up_sync(0xffu, w, off);
            if (lane >= off) w += y;
        }
        s_warp[lane] = w;
    }
    __syncthreads();
    int warpoff = (wid > 0) ? s_warp[wid - 1] : 0;
    int excl = warpoff + incl - tsum;

    int run = excl;
    #pragma unroll
    for (int k = 0; k < 4; ++k) {
        int i = base + k;
        if (i < N_NODES) {
            g_row[i]  = run;
            g_dinv[i] = rsqrtf((float)(v[k] + 1));
        }
        run += v[k];
    }
    if (t == 255) g_bsum[blockIdx.x] = s_warp[7];
}

__global__ __launch_bounds__(128) void scanB_kernel() {
    int t = threadIdx.x;
    int lane = t & 31, wid = t >> 5;
    __shared__ int s_warp[4];
    int v = (t < NB_SCAN) ? g_bsum[t] : 0;
    int incl = v;
    #pragma unroll
    for (int off = 1; off < 32; off <<= 1) {
        int y = __shfl_up_sync(0xffffffffu, incl, off);
        if (lane >= off) incl += y;
    }
    if (lane == 31) s_warp[wid] = incl;
    __syncthreads();
    if (wid == 0 && lane < 4) {
        int w = s_warp[lane];
        #pragma unroll
        for (int off = 1; off < 4; off <<= 1) {
            int y = __shfl_up_sync(0xfu, w, off);
            if (lane >= off) w += y;
        }
        s_warp[lane] = w;
    }
    __syncthreads();
    int warpoff = (wid > 0) ? s_warp[wid - 1] : 0;
    if (t < NB_SCAN) g_boff[t] = warpoff + incl - v;
    if (t == 0) g_row[N_NODES] = s_warp[3];
}

__global__ __launch_bounds__(256) void scanC_kernel() {
    int i = blockIdx.x * blockDim.x + threadIdx.x;
    if (i >= N_NODES) return;
    int r = g_row[i] + g_boff[i >> 10];
    g_row[i] = r;
    g_cursor[i] = r;
}

// 4 edges per thread via int4 loads of src and dst
__global__ __launch_bounds__(256) void reorder_kernel(
    const int* __restrict__ src, const int* __restrict__ dst, int E)
{
    int t = blockIdx.x * 256 + threadIdx.x;
    int base = t * 4;
    if (base + 3 < E) {
        int4 d = __ldg((const int4*)(dst + base));
        int4 s = __ldg((const int4*)(src + base));
        int p0 = atomicAdd(&g_cursor[d.x], 1);
        int p1 = atomicAdd(&g_cursor[d.y], 1);
        int p2 = atomicAdd(&g_cursor[d.z], 1);
        int p3 = atomicAdd(&g_cursor[d.w], 1);
        g_ssrc[p0] = s.x;
        g_ssrc[p1] = s.y;
        g_ssrc[p2] = s.z;
        g_ssrc[p3] = s.w;
    } else {
        for (int e = base; e < E; ++e) {
            int d = dst[e];
            int s = src[e];
            int pos = atomicAdd(&g_cursor[d], 1);
            g_ssrc[pos] = s;
        }
    }
}

// ---------------- GEMM1 (tf32 tensor cores): h = (x @ W1) * dinv -> fp16 ----------------
#define BM 128
#define BK 32
#define XPITCH 36
#define WPITCH 40
#define NCHUNK ((F_IN + BK - 1) / BK)   // 45

__global__ __launch_bounds__(128) void gemm1_kernel(
    const float* __restrict__ x, const float* __restrict__ W1)
{
    __shared__ __align__(16) float Xs[2][BM][XPITCH];
    __shared__ __align__(16) float Ws[2][BK][WPITCH];

    const int tid  = threadIdx.x;
    const int lane = tid & 31;
    const int warp = tid >> 5;
    const int gid  = lane >> 2;
    const int tig  = lane & 3;
    const int row0 = blockIdx.x * BM;
    const int sh   = gid & 3;

    float acc[2][4][4];
    #pragma unroll
    for (int m = 0; m < 2; ++m)
        #pragma unroll
        for (int n = 0; n < 4; ++n)
            #pragma unroll
            for (int r = 0; r < 4; ++r) acc[m][n][r] = 0.f;

    auto issue_stage = [&](int chunk, int buf) {
        int k0 = chunk * BK;
        #pragma unroll
        for (int i = 0; i < 8; ++i) {
            int r  = i * 16 + (tid >> 3);
            int j0 = (tid & 7) * 4;
            int grow = row0 + r;
            const float* srcp = x;
            int valid = 0;
            if (grow < N_NODES) {
                int shift = grow & 3;
                int col = k0 - shift + j0;
                int vb = (F_IN - col) * 4;
                valid = vb < 0 ? 0 : (vb > 16 ? 16 : vb);
                srcp = x + ((size_t)grow * F_IN + col);
            }
            cp_async16(&Xs[buf][r][j0], srcp, valid);
        }
        {
            int r = tid;
            int grow = row0 + r;
            const float* srcp = x;
            int valid = 0;
            int shift = grow & 3;
            if (grow < N_NODES && shift > 0) {
                int col = k0 - shift + 32;
                int vb = (F_IN - col) * 4;
                valid = vb < 0 ? 0 : (vb > 16 ? 16 : vb);
                srcp = x + ((size_t)grow * F_IN + col);
            }
            cp_async16(&Xs[buf][r][32], srcp, valid);
        }
        #pragma unroll
        for (int i = 0; i < 2; ++i) {
            int lin = i * 128 + tid;
            int kw = lin >> 3;
            int j = lin & 7;
            int gk = k0 + kw;
            int valid = (gk < F_IN) ? 16 : 0;
            const float* srcp = W1 + (size_t)(valid ? gk : 0) * F_H + j * 4;
            cp_async16(&Ws[buf][kw][j * 4], srcp, valid);
        }
    };

    issue_stage(0, 0);
    cp_commit();

    for (int c = 0; c < NCHUNK; ++c) {
        int buf = c & 1;
        bool more = (c + 1 < NCHUNK);
        if (more) { issue_stage(c + 1, buf ^ 1); cp_commit(); }
        if (more) cp_wait1(); else cp_wait0();
        __syncthreads();

        const int wr = warp * 32;
        #pragma unroll
        for (int ks = 0; ks < 4; ++ks) {
            int kb = ks * 8;
            unsigned afr[2][4];
            #pragma unroll
            for (int m = 0; m < 2; ++m) {
                int rb = wr + m * 16;
                afr[m][0] = __float_as_uint(Xs[buf][rb + gid    ][kb + tig + sh    ]);
                afr[m][1] = __float_as_uint(Xs[buf][rb + gid + 8][kb + tig + sh    ]);
                afr[m][2] = __float_as_uint(Xs[buf][rb + gid    ][kb + tig + sh + 4]);
                afr[m][3] = __float_as_uint(Xs[buf][rb + gid + 8][kb + tig + sh + 4]);
            }
            #pragma unroll
            for (int n = 0; n < 4; ++n) {
                unsigned bfr[2];
                bfr[0] = __float_as_uint(Ws[buf][kb + tig    ][n * 8 + gid]);
                bfr[1] = __float_as_uint(Ws[buf][kb + tig + 4][n * 8 + gid]);
                mma_tf32(acc[0][n], afr[0], bfr);
                mma_tf32(acc[1][n], afr[1], bfr);
            }
        }
        __syncthreads();
    }

    // epilogue: scale by dinv[row], convert to fp16, store __half2
    #pragma unroll
    for (int m = 0; m < 2; ++m) {
        int r0r = row0 + warp * 32 + m * 16 + gid;
        int r1r = r0r + 8;
        float w0 = (r0r < N_NODES) ? g_dinv[r0r] : 0.f;
        float w1 = (r1r < N_NODES) ? g_dinv[r1r] : 0.f;
        #pragma unroll
        for (int n = 0; n < 4; ++n) {
            int col = n * 8 + tig * 2;
            if (r0r < N_NODES)
                *(__half2*)&g_hh[(size_t)r0r * F_H + col] =
                    __floats2half2_rn(acc[m][n][0] * w0, acc[m][n][1] * w0);
            if (r1r < N_NODES)
                *(__half2*)&g_hh[(size_t)r1r * F_H + col] =
                    __floats2half2_rn(acc[m][n][2] * w1, acc[m][n][3] * w1);
        }
    }
}

// ------- gather + node1 fused: 4 threads/node, 4-way unrolled, fp16 h -------
// Each thread owns 8 consecutive h-features (one uint4 = 16B of fp16).
__device__ __forceinline__ void acc_h8(float* a, uint4 p) {
    float2 f0 = __half22float2(*(__half2*)&p.x);
    float2 f1 = __half22float2(*(__half2*)&p.y);
    float2 f2 = __half22float2(*(__half2*)&p.z);
    float2 f3 = __half22float2(*(__half2*)&p.w);
    a[0] += f0.x; a[1] += f0.y; a[2] += f1.x; a[3] += f1.y;
    a[4] += f2.x; a[5] += f2.y; a[6] += f3.x; a[7] += f3.y;
}

__global__ __launch_bounds__(256) void gather_node1_kernel(
    const float* __restrict__ b1, const float* __restrict__ W2)
{
    __shared__ float sW2[F_H * F_OUT];
    __shared__ float sb1[F_H];
    int tid = threadIdx.x;
    if (tid < F_H * F_OUT) sW2[tid] = W2[tid];
    if (tid < F_H)         sb1[tid] = b1[tid];
    __syncthreads();

    int i = blockIdx.x * 64 + (tid >> 2);   // 64 nodes per block
    int q = tid & 3;                        // 16B chunk (8 features)
    if (i >= N_NODES) return;

    int beg = g_row[i];
    int end = g_row[i + 1];

    float a[8];
    #pragma unroll
    for (int t = 0; t < 8; ++t) a[t] = 0.f;
    acc_h8(a, __ldg(((const uint4*)(g_hh + (size_t)i * F_H)) + q));   // self term

    int j = beg;
    for (; j + 4 <= end; j += 4) {
        int s0 = __ldg(&g_ssrc[j    ]);
        int s1 = __ldg(&g_ssrc[j + 1]);
        int s2 = __ldg(&g_ssrc[j + 2]);
        int s3 = __ldg(&g_ssrc[j + 3]);
        uint4 p0 = __ldg(((const uint4*)(g_hh + (size_t)s0 * F_H)) + q);
        uint4 p1 = __ldg(((const uint4*)(g_hh + (size_t)s1 * F_H)) + q);
        uint4 p2 = __ldg(((const uint4*)(g_hh + (size_t)s2 * F_H)) + q);
        uint4 p3 = __ldg(((const uint4*)(g_hh + (size_t)s3 * F_H)) + q);
        acc_h8(a, p0);
        acc_h8(a, p1);
        acc_h8(a, p2);
        acc_h8(a, p3);
    }
    for (; j < end; ++j) {
        int s = __ldg(&g_ssrc[j]);
        acc_h8(a, __ldg(((const uint4*)(g_hh + (size_t)s * F_H)) + q));
    }

    float di = g_dinv[i];
    float o[F_OUT];
    #pragma unroll
    for (int c = 0; c < F_OUT; ++c) o[c] = 0.f;
    #pragma unroll
    for (int t = 0; t < 8; ++t) {
        int f = q * 8 + t;
        float hr = fmaxf(a[t] * di + sb1[f], 0.f);
        #pragma unroll
        for (int c = 0; c < F_OUT; ++c)
            o[c] += hr * sW2[f * F_OUT + c];
    }
    // reduce over the 4 lanes of this node
    #pragma unroll
    for (int d = 2; d >= 1; d >>= 1)
        #pragma unroll
        for (int c = 0; c < F_OUT; ++c)
            o[c] += __shfl_down_sync(0xffffffffu, o[c], d, 4);

    if (q == 0) {
        __half2 p0 = __floats2half2_rn(o[0] * di, o[1] * di);
        __half2 p1 = __floats2half2_rn(o[2] * di, o[3] * di);
        __half2 p2 = __floats2half2_rn(o[4] * di, o[5] * di);
        __half2 p3 = __floats2half2_rn(o[6] * di, 0.f);
        uint4 pk;
        pk.x = *(unsigned*)&p0; pk.y = *(unsigned*)&p1;
        pk.z = *(unsigned*)&p2; pk.w = *(unsigned*)&p3;
        *(uint4*)(g_h2h + (size_t)i * 8) = pk;
    }
}

// ------- gather + final fused: 1 thread/node, 4-way unrolled, fp16 h2 -------
__device__ __forceinline__ void acc_half7(float* a, uint4 p) {
    float2 f0 = __half22float2(*(__half2*)&p.x);
    float2 f1 = __half22float2(*(__half2*)&p.y);
    float2 f2 = __half22float2(*(__half2*)&p.z);
    float2 f3 = __half22float2(*(__half2*)&p.w);
    a[0] += f0.x; a[1] += f0.y; a[2] += f1.x; a[3] += f1.y;
    a[4] += f2.x; a[5] += f2.y; a[6] += f3.x;
}

__global__ __launch_bounds__(256) void gather_final_kernel(
    const float* __restrict__ b2, float* __restrict__ out)
{
    int i = blockIdx.x * blockDim.x + threadIdx.x;
    if (i >= N_NODES) return;
    int beg = g_row[i];
    int end = g_row[i + 1];

    float a[F_OUT];
    #pragma unroll
    for (int c = 0; c < F_OUT; ++c) a[c] = 0.f;
    acc_half7(a, __ldg((const uint4*)(g_h2h + (size_t)i * 8)));   // self

    int j = beg;
    for (; j + 4 <= end; j += 4) {
        int s0 = __ldg(&g_ssrc[j]);
        int s1 = __ldg(&g_ssrc[j + 1]);
        int s2 = __ldg(&g_ssrc[j + 2]);
        int s3 = __ldg(&g_ssrc[j + 3]);
        uint4 p0 = __ldg((const uint4*)(g_h2h + (size_t)s0 * 8));
        uint4 p1 = __ldg((const uint4*)(g_h2h + (size_t)s1 * 8));
        uint4 p2 = __ldg((const uint4*)(g_h2h + (size_t)s2 * 8));
        uint4 p3 = __ldg((const uint4*)(g_h2h + (size_t)s3 * 8));
        acc_half7(a, p0);
        acc_half7(a, p1);
        acc_half7(a, p2);
        acc_half7(a, p3);
    }
    for (; j < end; ++j) {
        int s = __ldg(&g_ssrc[j]);
        acc_half7(a, __ldg((const uint4*)(g_h2h + (size_t)s * 8)));
    }

    float di = g_dinv[i];
    float v[F_OUT];
    #pragma unroll
    for (int c = 0; c < F_OUT; ++c) v[c] = a[c] * di + b2[c];
    float m = v[0];
    #pragma unroll
    for (int c = 1; c < F_OUT; ++c) m = fmaxf(m, v[c]);
    float s = 0.f;
    #pragma unroll
    for (int c = 0; c < F_OUT; ++c) s += expf(v[c] - m);
    float lse = m + logf(s);
    float* o = out + (size_t)i * F_OUT;
    #pragma unroll
    for (int c = 0; c < F_OUT; ++c) o[c] = v[c] - lse;
}

// ---------------- launch ----------------
extern "C" void kernel_launch(void* const* d_in, const int* in_sizes, int n_in,
                              void* d_out, int out_size)
{
    const float* x   = (const float*)d_in[0];
    const int*   ei  = (const int*)  d_in[1];
    const float* W1  = (const float*)d_in[2];
    const float* b1  = (const float*)d_in[3];
    const float* W2  = (const float*)d_in[4];
    const float* b2  = (const float*)d_in[5];
    float* out = (float*)d_out;

    const int E = in_sizes[1] / 2;
    const int* src = ei;
    const int* dst = ei + E;

    int nb_n  = (N_NODES + 255) / 256;
    int nb_v4 = ((E + 3) / 4 + 255) / 256;

    zero_kernel<<<nb_n, 256>>>();
    hist_kernel<<<nb_v4, 256>>>(dst, E);
    scanA_kernel<<<NB_SCAN, 256>>>();
    scanB_kernel<<<1, 128>>>();
    scanC_kernel<<<nb_n, 256>>>();
    reorder_kernel<<<nb_v4, 256>>>(src, dst, E);

    int nb_g = (N_NODES + BM - 1) / BM;
    gemm1_kernel<<<nb_g, 128>>>(x, W1);

    gather_node1_kernel<<<(N_NODES + 63) / 64, 256>>>(b1, W2);

    gather_final_kernel<<<nb_n, 256>>>(b2, out);
}